// round 1
// baseline (speedup 1.0000x reference)
#include <cuda_runtime.h>
#include <math.h>
#include <stdint.h>

#define NB   256
#define NN   102400
#define EE   819200
#define ETOT (EE + NN)
#define PADT 512

#define OFF_CNN ((size_t)0)
#define OFF_OG  ((size_t)NB * PADT * 128)
#define OFF_M1  (OFF_OG * 2)
#define OFF_M2  (OFF_M1 + (size_t)NB * PADT)
#define OFF_ES  (OFF_M2 + (size_t)NB * PADT)
#define OFF_EG  (OFF_ES + (size_t)NB * 128)

// ---------------- scratch (device globals: no allocs allowed) ----------------
__device__ float g_h  [(size_t)NN * 1024];
__device__ float g_x1 [(size_t)NN * 256];
__device__ float g_x2 [(size_t)NN * 256];
__device__ float g_as [NN * 4];
__device__ float g_ad [NN * 4];
__device__ float g_hf [(size_t)NN * 128];
__device__ float g_e2 [(size_t)NN * 128];
__device__ float g_cin[(size_t)NB * PADT * 128];
__device__ float g_y  [(size_t)NB * PADT * 64];
__device__ float g_hid[(size_t)NB * PADT * 512];
__device__ float g_wt [128 * 15 * 64];
__device__ float g_bt [64];
__device__ int   g_deg[NN];
__device__ int   g_indptr[NN + 1];
__device__ int   g_pos[NN];
__device__ int   g_col[ETOT];
__device__ int   g_off[NB];
__device__ float g_cnt[NB];
__device__ int   g_bsum[128];

// ---------------- CSR construction ----------------
__global__ void k_deg_init() {
    int i = blockIdx.x * 256 + threadIdx.x;
    if (i < NN) g_deg[i] = 1;   // self-loop
}
__global__ void k_deg_count(const int* __restrict__ ei) {
    int e = blockIdx.x * 256 + threadIdx.x;
    if (e < EE) atomicAdd(&g_deg[ei[EE + e]], 1);
}
__global__ void k_scan_block(const int* __restrict__ in, int* __restrict__ out,
                             int* __restrict__ bsums, int n) {
    __shared__ int sh[1024];
    int tid = threadIdx.x;
    int i = blockIdx.x * 1024 + tid;
    int v = (i < n) ? in[i] : 0;
    sh[tid] = v;
    __syncthreads();
    for (int o = 1; o < 1024; o <<= 1) {
        int t = (tid >= o) ? sh[tid - o] : 0;
        __syncthreads();
        sh[tid] += t;
        __syncthreads();
    }
    if (i < n) out[i] = sh[tid] - v;               // exclusive
    if (tid == 1023 && bsums) bsums[blockIdx.x] = sh[1023];
}
__global__ void k_scan_bsums(int* bsums, int nb) {
    __shared__ int sh[1024];
    int tid = threadIdx.x;
    int v = (tid < nb) ? bsums[tid] : 0;
    sh[tid] = v;
    __syncthreads();
    for (int o = 1; o < 1024; o <<= 1) {
        int t = (tid >= o) ? sh[tid - o] : 0;
        __syncthreads();
        sh[tid] += t;
        __syncthreads();
    }
    if (tid < nb) bsums[tid] = sh[tid] - v;
}
__global__ void k_scan_add(int* out, const int* bsums, int n) {
    int i = blockIdx.x * 1024 + threadIdx.x;
    if (i < n) out[i] += bsums[blockIdx.x];
}
__global__ void k_settot() { g_indptr[NN] = ETOT; }
__global__ void k_fill_self() {
    int i = blockIdx.x * 256 + threadIdx.x;
    if (i < NN) {
        int p = g_indptr[i];
        g_col[p] = i;          // self loop first
        g_pos[i] = p + 1;
    }
}
__global__ void k_fill_edges(const int* __restrict__ ei) {
    int e = blockIdx.x * 256 + threadIdx.x;
    if (e < EE) {
        int d = ei[EE + e];
        int p = atomicAdd(&g_pos[d], 1);
        g_col[p] = ei[e];
    }
}
__global__ void k_zero_cnt() { g_cnt[threadIdx.x] = 0.f; }
__global__ void k_cnt(const int* __restrict__ batch) {
    int i = blockIdx.x * 256 + threadIdx.x;
    if (i < NN) atomicAdd(&g_cnt[batch[i]], 1.0f);
}

// ---------------- gathers ----------------
__global__ void k_gather_g(const int* __restrict__ x, const float* __restrict__ tabg,
                           float* __restrict__ out) {
    int i = blockIdx.x * 256 + threadIdx.x;
    if (i < NN * 128) {
        int nd = i >> 7, c = i & 127;
        out[i] = tabg[x[nd] * 128 + c];
    }
}

// ---------------- generic tiled fp32 GEMM: C[M,N] = A[M,K] @ B[K,N] ----------------
// BM=128 BN=64 BK=16, 256 threads, 8x4 per thread. M%128==0, N%64==0, K%16==0.
__global__ void __launch_bounds__(256) k_gemm(
    const float* __restrict__ A, const float* __restrict__ Bm, float* __restrict__ C,
    int M, int Nc, int K, const float* __restrict__ bias, int doRelu)
{
    __shared__ float As[16][132];
    __shared__ float Bs[16][64];
    int tid = threadIdx.x;
    int row0 = blockIdx.y * 128;
    int col0 = blockIdx.x * 64;
    int ty = tid >> 4, tx = tid & 15;
    int am = tid >> 2, akv = (tid & 3) * 4;
    int bk = tid >> 4, bcv = (tid & 15) * 4;
    float acc[8][4];
#pragma unroll
    for (int i = 0; i < 8; i++)
#pragma unroll
        for (int j = 0; j < 4; j++) acc[i][j] = 0.f;

    for (int k0 = 0; k0 < K; k0 += 16) {
        float4 a0 = *(const float4*)&A[((size_t)(row0 + am)) * K + k0 + akv];
        float4 a1 = *(const float4*)&A[((size_t)(row0 + am + 64)) * K + k0 + akv];
        As[akv + 0][am] = a0.x; As[akv + 1][am] = a0.y;
        As[akv + 2][am] = a0.z; As[akv + 3][am] = a0.w;
        As[akv + 0][am + 64] = a1.x; As[akv + 1][am + 64] = a1.y;
        As[akv + 2][am + 64] = a1.z; As[akv + 3][am + 64] = a1.w;
        float4 b = *(const float4*)&Bm[((size_t)(k0 + bk)) * Nc + col0 + bcv];
        *(float4*)&Bs[bk][bcv] = b;
        __syncthreads();
#pragma unroll
        for (int kk = 0; kk < 16; kk++) {
            float ar[8], br[4];
            *(float4*)&ar[0] = *(float4*)&As[kk][ty * 8];
            *(float4*)&ar[4] = *(float4*)&As[kk][ty * 8 + 4];
            *(float4*)&br[0] = *(float4*)&Bs[kk][tx * 4];
#pragma unroll
            for (int i = 0; i < 8; i++)
#pragma unroll
                for (int j = 0; j < 4; j++) acc[i][j] += ar[i] * br[j];
        }
        __syncthreads();
    }
#pragma unroll
    for (int i = 0; i < 8; i++) {
        size_t r = row0 + ty * 8 + i;
#pragma unroll
        for (int j = 0; j < 4; j++) {
            int c = col0 + tx * 4 + j;
            float v = acc[i][j];
            if (bias) v += bias[c];
            if (doRelu) v = fmaxf(v, 0.f);
            C[r * Nc + c] = v;
        }
    }
}

// ---------------- attention logits: a_s/a_d per (node, head) ----------------
__global__ void k_attn(const float* __restrict__ Hm, const float* __restrict__ aw,
                       const float* __restrict__ dw, int heads, int C)
{
    int n = blockIdx.x;
    int h = threadIdx.x >> 5, lane = threadIdx.x & 31;
    const float* hp = Hm + ((size_t)n * heads + h) * C;
    const float* ap = aw + h * C;
    const float* dp = dw + h * C;
    float s = 0.f, d = 0.f;
    for (int c = lane; c < C; c += 32) {
        float v = hp[c];
        s += v * ap[c];
        d += v * dp[c];
    }
    for (int o = 16; o; o >>= 1) {
        s += __shfl_xor_sync(0xFFFFFFFFu, s, o);
        d += __shfl_xor_sync(0xFFFFFFFFu, d, o);
    }
    if (!lane) { g_as[n * heads + h] = s; g_ad[n * heads + h] = d; }
}

__device__ __forceinline__ float lrelu(float z) { return z >= 0.f ? z : 0.2f * z; }

// ---------------- GAT aggregation, heads=4, C=256: out = relu(mean_h(softmax-agg) + bias) ----
__global__ void __launch_bounds__(256) k_agg4(const float* __restrict__ Hm,
                                              const float* __restrict__ bias,
                                              float* __restrict__ out)
{
    int n = blockIdx.x, tid = threadIdx.x;
    int e0 = g_indptr[n], deg = g_indptr[n + 1] - e0;
    __shared__ float sm[4], sden[4];
    __shared__ float salpha[64 * 4];
    __shared__ int   ssrc[64];
    __shared__ float sacc[4][256];
    if (tid < 4) {
        int h = tid;
        float ad = g_ad[n * 4 + h];
        float m = -INFINITY, s = 0.f;
        for (int j = 0; j < deg; j++) {
            int src = g_col[e0 + j];
            float e = lrelu(g_as[src * 4 + h] + ad);
            if (e > m) { s = s * expf(m - e) + 1.0f; m = e; }
            else       { s += expf(e - m); }
        }
        sm[h] = m; sden[h] = fmaxf(s, 1e-16f);
    }
    __syncthreads();
    int h = tid >> 6;
    int cb = (tid & 63) * 4;
    float4 acc = make_float4(0.f, 0.f, 0.f, 0.f);
    for (int base = 0; base < deg; base += 64) {
        int cn = min(64, deg - base);
        if (tid < cn) ssrc[tid] = g_col[e0 + base + tid];
        __syncthreads();
        if (tid < cn * 4) {
            int j = tid >> 2, hh = tid & 3;
            float e = lrelu(g_as[ssrc[j] * 4 + hh] + g_ad[n * 4 + hh]);
            salpha[j * 4 + hh] = expf(e - sm[hh]) / sden[hh];
        }
        __syncthreads();
        for (int j = 0; j < cn; j++) {
            float a = salpha[j * 4 + h];
            float4 hv = *(const float4*)&Hm[((size_t)ssrc[j] * 4 + h) * 256 + cb];
            acc.x += a * hv.x; acc.y += a * hv.y;
            acc.z += a * hv.z; acc.w += a * hv.w;
        }
        __syncthreads();
    }
    *(float4*)&sacc[h][cb] = acc;
    __syncthreads();
    int c = tid;
    float v = (sacc[0][c] + sacc[1][c] + sacc[2][c] + sacc[3][c]) * 0.25f + bias[c];
    out[(size_t)n * 256 + c] = fmaxf(v, 0.f);
}

// ---------------- GAT aggregation, heads=1, C=128 ----------------
__global__ void __launch_bounds__(128) k_agg1(const float* __restrict__ Hm,
                                              const float* __restrict__ bias,
                                              float* __restrict__ out)
{
    int n = blockIdx.x, tid = threadIdx.x;
    int e0 = g_indptr[n], deg = g_indptr[n + 1] - e0;
    __shared__ float sm1, sden1;
    __shared__ float salpha[128];
    __shared__ int   ssrc[128];
    if (tid == 0) {
        float ad = g_ad[n];
        float m = -INFINITY, s = 0.f;
        for (int j = 0; j < deg; j++) {
            int src = g_col[e0 + j];
            float e = lrelu(g_as[src] + ad);
            if (e > m) { s = s * expf(m - e) + 1.0f; m = e; }
            else       { s += expf(e - m); }
        }
        sm1 = m; sden1 = fmaxf(s, 1e-16f);
    }
    __syncthreads();
    float acc = 0.f;
    for (int base = 0; base < deg; base += 128) {
        int cn = min(128, deg - base);
        if (tid < cn) {
            int src = g_col[e0 + base + tid];
            ssrc[tid] = src;
            float e = lrelu(g_as[src] + g_ad[n]);
            salpha[tid] = expf(e - sm1) / sden1;
        }
        __syncthreads();
        for (int j = 0; j < cn; j++)
            acc += salpha[j] * Hm[(size_t)ssrc[j] * 128 + tid];
        __syncthreads();
    }
    out[(size_t)n * 128 + tid] = fmaxf(acc + bias[tid], 0.f);
}

// ---------------- out_graph + masks ----------------
__global__ void k_outgraph(const int* __restrict__ node_len, float* __restrict__ out)
{
    int t = blockIdx.x, b = blockIdx.y, c = threadIdx.x;
    int len = node_len[b];
    float v = 0.f;
    if (t < len) v = g_hf[(size_t)(g_off[b] + t) * 128 + c];
    out[OFF_OG + ((size_t)b * PADT + t) * 128 + c] = v;
    if (c == 0) {
        float mk = (t < len) ? 1.f : 0.f;
        out[OFF_M1 + (size_t)b * PADT + t] = mk;
        out[OFF_M2 + (size_t)b * PADT + t] = mk;
    }
}
__global__ void k_embgraph(const int* __restrict__ node_len, float* __restrict__ out)
{
    int b = blockIdx.x, c = threadIdx.x;
    int len = node_len[b], off = g_off[b];
    float s = 0.f;
    for (int t = 0; t < len; t++) s += g_hf[(size_t)(off + t) * 128 + c];
    out[OFF_EG + (size_t)b * 128 + c] = s / g_cnt[b];
}

// ---------------- conv input: out_r = (x_r + emb2)/2, padded ----------------
__global__ void k_outr(const int* __restrict__ x, const float* __restrict__ tabr,
                       const int* __restrict__ node_len)
{
    int t = blockIdx.x, b = blockIdx.y, c = threadIdx.x;
    int len = node_len[b];
    float v = 0.f;
    if (t < len) {
        int nd = g_off[b] + t;
        v = 0.5f * (tabr[(size_t)x[nd] * 128 + c] + g_e2[(size_t)nd * 128 + c]);
    }
    g_cin[((size_t)b * PADT + t) * 128 + c] = v;
}

// ---------------- fold the three convs into one 15-tap filter, layout [ch][tap][out] ----
__global__ void k_wcomb(const float* __restrict__ cw1, const float* __restrict__ cb1,
                        const float* __restrict__ cw2, const float* __restrict__ cb2,
                        const float* __restrict__ cw3, const float* __restrict__ cb3)
{
    int i = blockIdx.x * 256 + threadIdx.x;
    if (i >= 128 * 15 * 64) return;
    int o = i & 63;
    int r = i >> 6;
    int d = r % 15;
    int ch = r / 15;
    int dd = d - 7;
    float w = cw3[((size_t)o * 128 + ch) * 15 + d];
    if (dd >= -5 && dd <= 5) w += cw2[((size_t)o * 128 + ch) * 11 + (dd + 5)];
    if (dd >= -3 && dd <= 3) w += cw1[((size_t)o * 128 + ch) * 7 + (dd + 3)];
    g_wt[(ch * 15 + d) * 64 + o] = w * (1.f / 3.f);
    if (i < 64) g_bt[i] = (cb1[i] + cb2[i] + cb3[i]) * (1.f / 3.f);
}

// ---------------- 15-tap conv, 128 in ch -> 64 out ch, per (batch, 64-wide t tile) ----
__global__ void __launch_bounds__(256) k_conv()
{
    __shared__ float xs[78][128];
    int b = blockIdx.y;
    int t0 = blockIdx.x * 64;
    int tid = threadIdx.x;
    for (int l = tid; l < 78 * 32; l += 256) {
        int r = l >> 5, c4 = l & 31;
        int t = t0 - 7 + r;
        float4 v = make_float4(0.f, 0.f, 0.f, 0.f);
        if (t >= 0 && t < PADT)
            v = *(const float4*)&g_cin[((size_t)b * PADT + t) * 128 + c4 * 4];
        *(float4*)&xs[r][c4 * 4] = v;
    }
    __syncthreads();
    int o = tid & 63;
    int tb = (tid >> 6) * 16;
    float acc[16];
#pragma unroll
    for (int i = 0; i < 16; i++) acc[i] = 0.f;
    for (int ch = 0; ch < 128; ch++) {
        float xr[30];
#pragma unroll
        for (int r = 0; r < 30; r++) xr[r] = xs[tb + r][ch];
#pragma unroll
        for (int d = 0; d < 15; d++) {
            float wv = g_wt[(ch * 15 + d) * 64 + o];
#pragma unroll
            for (int tt = 0; tt < 16; tt++) acc[tt] += wv * xr[tt + d];
        }
    }
    float bb = g_bt[o];
#pragma unroll
    for (int tt = 0; tt < 16; tt++)
        g_y[((size_t)b * PADT + t0 + tb + tt) * 64 + o] = acc[tt] + bb;
}

// ---------------- emb_seq: masked mean over PAD of out_seq_cnn ----------------
__global__ void k_embseq(const int* __restrict__ node_len, float* __restrict__ out)
{
    int b = blockIdx.x, c = threadIdx.x;
    int len = node_len[b];
    const float* p = out + OFF_CNN + (size_t)b * PADT * 128 + c;
    float s = 0.f;
    for (int t = 0; t < len; t++) s += p[(size_t)t * 128];
    out[OFF_ES + (size_t)b * 128 + c] = s * (1.0f / PADT);
}

// ======================== host ========================
extern "C" void kernel_launch(void* const* d_in, const int* in_sizes, int n_in,
                              void* d_out, int out_size)
{
    const int*   x        = (const int*)d_in[0];
    const int*   ei       = (const int*)d_in[1];
    const float* emb      = (const float*)d_in[2];
    const int*   node_len = (const int*)d_in[3];
    const int*   batch    = (const int*)d_in[4];
    const float* tab_r    = (const float*)d_in[5];
    const float* tab_g    = (const float*)d_in[6];
    const float* W1  = (const float*)d_in[7];
    const float* a1s = (const float*)d_in[8];
    const float* a1d = (const float*)d_in[9];
    const float* b1  = (const float*)d_in[10];
    const float* W2  = (const float*)d_in[11];
    const float* a2s = (const float*)d_in[12];
    const float* a2d = (const float*)d_in[13];
    const float* b2  = (const float*)d_in[14];
    const float* W3  = (const float*)d_in[15];
    const float* a3s = (const float*)d_in[16];
    const float* a3d = (const float*)d_in[17];
    const float* b3  = (const float*)d_in[18];
    const float* leW = (const float*)d_in[19];
    const float* leb = (const float*)d_in[20];
    const float* cw1 = (const float*)d_in[21];
    const float* cb1 = (const float*)d_in[22];
    const float* cw2 = (const float*)d_in[23];
    const float* cb2 = (const float*)d_in[24];
    const float* cw3 = (const float*)d_in[25];
    const float* cb3 = (const float*)d_in[26];
    const float* l1W = (const float*)d_in[27];
    const float* l1b = (const float*)d_in[28];
    const float* l2W = (const float*)d_in[29];
    const float* l2b = (const float*)d_in[30];
    float* out = (float*)d_out;

    float *ph, *px1, *px2, *pe2, *py, *phid, *phf;
    int *pdeg, *pind, *pbs;
    cudaGetSymbolAddress((void**)&ph,   g_h);
    cudaGetSymbolAddress((void**)&px1,  g_x1);
    cudaGetSymbolAddress((void**)&px2,  g_x2);
    cudaGetSymbolAddress((void**)&pe2,  g_e2);
    cudaGetSymbolAddress((void**)&py,   g_y);
    cudaGetSymbolAddress((void**)&phid, g_hid);
    cudaGetSymbolAddress((void**)&phf,  g_hf);
    cudaGetSymbolAddress((void**)&pdeg, g_deg);
    cudaGetSymbolAddress((void**)&pind, g_indptr);
    cudaGetSymbolAddress((void**)&pbs,  g_bsum);
    int *poff;
    cudaGetSymbolAddress((void**)&poff, g_off);

    // ---- CSR build (by dst, self-loop in slot 0) ----
    k_deg_init<<<NN / 256, 256>>>();
    k_deg_count<<<EE / 256, 256>>>(ei);
    k_scan_block<<<100, 1024>>>(pdeg, pind, pbs, NN);
    k_scan_bsums<<<1, 1024>>>(pbs, 100);
    k_scan_add<<<100, 1024>>>(pind, pbs, NN);
    k_settot<<<1, 1>>>();
    k_fill_self<<<NN / 256, 256>>>();
    k_fill_edges<<<EE / 256, 256>>>(ei);

    // ---- offsets / counts ----
    k_scan_block<<<1, 1024>>>(node_len, poff, nullptr, NB);
    k_zero_cnt<<<1, NB>>>();
    k_cnt<<<NN / 256, 256>>>(batch);

    // ---- GAT layer 1 ----
    k_gather_g<<<(NN * 128) / 256, 256>>>(x, tab_g, px1);
    k_gemm<<<dim3(1024 / 64, NN / 128), 256>>>(px1, W1, ph, NN, 1024, 128, nullptr, 0);
    k_attn<<<NN, 128>>>(ph, a1s, a1d, 4, 256);
    k_agg4<<<NN, 256>>>(ph, b1, px2);

    // ---- GAT layer 2 ----
    k_gemm<<<dim3(1024 / 64, NN / 128), 256>>>(px2, W2, ph, NN, 1024, 256, nullptr, 0);
    k_attn<<<NN, 128>>>(ph, a2s, a2d, 4, 256);
    k_agg4<<<NN, 256>>>(ph, b2, px1);

    // ---- GAT layer 3 ----
    k_gemm<<<dim3(128 / 64, NN / 128), 256>>>(px1, W3, ph, NN, 128, 256, nullptr, 0);
    k_attn<<<NN, 32>>>(ph, a3s, a3d, 1, 128);
    k_agg1<<<NN, 128>>>(ph, b3, phf);

    // ---- graph outputs ----
    k_outgraph<<<dim3(PADT, NB), 128>>>(node_len, out);
    k_embgraph<<<NB, 128>>>(node_len, out);

    // ---- sequence branch ----
    k_gemm<<<dim3(128 / 64, NN / 128), 256>>>(emb, leW, pe2, NN, 128, 640, leb, 1);
    k_outr<<<dim3(PADT, NB), 128>>>(x, tab_r, node_len);
    k_wcomb<<<480, 256>>>(cw1, cb1, cw2, cb2, cw3, cb3);
    k_conv<<<dim3(PADT / 64, NB), 256>>>();
    k_gemm<<<dim3(512 / 64, (NB * PADT) / 128), 256>>>(py, l1W, phid, NB * PADT, 512, 64, l1b, 1);
    k_gemm<<<dim3(128 / 64, (NB * PADT) / 128), 256>>>(phid, l2W, out, NB * PADT, 128, 512, l2b, 0);
    k_embseq<<<NB, 128>>>(node_len, out);
}

// round 2
// speedup vs baseline: 1.4391x; 1.4391x over previous
#include <cuda_runtime.h>
#include <math.h>
#include <stdint.h>

#define NB   256
#define NN   102400
#define EE   819200
#define ETOT (EE + NN)
#define PADT 512

#define OFF_CNN ((size_t)0)
#define OFF_OG  ((size_t)NB * PADT * 128)
#define OFF_M1  (OFF_OG * 2)
#define OFF_M2  (OFF_M1 + (size_t)NB * PADT)
#define OFF_ES  (OFF_M2 + (size_t)NB * PADT)
#define OFF_EG  (OFF_ES + (size_t)NB * 128)

// ---------------- scratch (device globals: no allocs allowed) ----------------
__device__ __align__(16) float g_h  [(size_t)NN * 1024];
__device__ __align__(16) float g_x1 [(size_t)NN * 256];
__device__ __align__(16) float g_x2 [(size_t)NN * 256];
__device__ __align__(16) float g_as [NN * 4];
__device__ __align__(16) float g_ad [NN * 4];
__device__ __align__(16) float g_hf [(size_t)NN * 128];
__device__ __align__(16) float g_e2 [(size_t)NN * 128];
__device__ __align__(16) float g_cin[(size_t)NB * PADT * 128];
__device__ __align__(16) float g_y  [(size_t)NB * PADT * 64];
__device__ __align__(16) float g_hid[(size_t)NB * PADT * 512];
__device__ __align__(16) float g_wt [128 * 15 * 64];
__device__ __align__(16) float g_bt [64];
__device__ int   g_deg[NN];
__device__ int   g_indptr[NN + 1];
__device__ int   g_pos[NN];
__device__ int   g_col[ETOT];
__device__ int   g_off[NB];
__device__ float g_cnt[NB];
__device__ int   g_bsum[128];

// ---------------- CSR construction ----------------
__global__ void k_deg_init() {
    int i = blockIdx.x * 256 + threadIdx.x;
    if (i < NN) g_deg[i] = 1;   // self-loop
}
__global__ void k_deg_count(const int* __restrict__ ei) {
    int e = blockIdx.x * 256 + threadIdx.x;
    if (e < EE) atomicAdd(&g_deg[ei[EE + e]], 1);
}
__global__ void k_scan_block(const int* __restrict__ in, int* __restrict__ out,
                             int* __restrict__ bsums, int n) {
    __shared__ int sh[1024];
    int tid = threadIdx.x;
    int i = blockIdx.x * 1024 + tid;
    int v = (i < n) ? in[i] : 0;
    sh[tid] = v;
    __syncthreads();
    for (int o = 1; o < 1024; o <<= 1) {
        int t = (tid >= o) ? sh[tid - o] : 0;
        __syncthreads();
        sh[tid] += t;
        __syncthreads();
    }
    if (i < n) out[i] = sh[tid] - v;               // exclusive
    if (tid == 1023 && bsums) bsums[blockIdx.x] = sh[1023];
}
__global__ void k_scan_bsums(int* bsums, int nb) {
    __shared__ int sh[1024];
    int tid = threadIdx.x;
    int v = (tid < nb) ? bsums[tid] : 0;
    sh[tid] = v;
    __syncthreads();
    for (int o = 1; o < 1024; o <<= 1) {
        int t = (tid >= o) ? sh[tid - o] : 0;
        __syncthreads();
        sh[tid] += t;
        __syncthreads();
    }
    if (tid < nb) bsums[tid] = sh[tid] - v;
}
__global__ void k_scan_add(int* out, const int* bsums, int n) {
    int i = blockIdx.x * 1024 + threadIdx.x;
    if (i < n) out[i] += bsums[blockIdx.x];
}
__global__ void k_settot() { g_indptr[NN] = ETOT; }
__global__ void k_fill_self() {
    int i = blockIdx.x * 256 + threadIdx.x;
    if (i < NN) {
        int p = g_indptr[i];
        g_col[p] = i;          // self loop first
        g_pos[i] = p + 1;
    }
}
__global__ void k_fill_edges(const int* __restrict__ ei) {
    int e = blockIdx.x * 256 + threadIdx.x;
    if (e < EE) {
        int d = ei[EE + e];
        int p = atomicAdd(&g_pos[d], 1);
        g_col[p] = ei[e];
    }
}
__global__ void k_zero_cnt() { g_cnt[threadIdx.x] = 0.f; }
__global__ void k_cnt(const int* __restrict__ batch) {
    int i = blockIdx.x * 256 + threadIdx.x;
    if (i < NN) atomicAdd(&g_cnt[batch[i]], 1.0f);
}

// ---------------- tf32 tensor-core GEMM ----------------
__device__ __forceinline__ unsigned f2tf(float x) {
    unsigned r; asm("cvt.rna.tf32.f32 %0, %1;" : "=r"(r) : "f"(x)); return r;
}
__device__ __forceinline__ void mma_tf32(float* c, const unsigned* a, const unsigned* b) {
    asm volatile("mma.sync.aligned.m16n8k8.row.col.f32.tf32.tf32.f32 "
        "{%0,%1,%2,%3},{%4,%5,%6,%7},{%8,%9},{%0,%1,%2,%3};"
        : "+f"(c[0]), "+f"(c[1]), "+f"(c[2]), "+f"(c[3])
        : "r"(a[0]), "r"(a[1]), "r"(a[2]), "r"(a[3]), "r"(b[0]), "r"(b[1]));
}

// C[M,Nc] = A[M,K] @ B[K,Nc] (+bias, relu). BM=128, BN=64, BK=16, 256 thr / 8 warps.
// CONV=1: implicit im2col over g_cin-style A: row -> (b,t), k -> (ch,d), elem = A[(b,t+d-7),ch].
// rowidx (CONV=0 only): A row = rowidx[out_row] (embedding-gather fusion).
template<int CONV>
__global__ void __launch_bounds__(256) k_gemm_tc(
    const float* __restrict__ A, const float* __restrict__ Bm, float* __restrict__ C,
    int M, int Nc, int K, const float* __restrict__ bias, int doRelu,
    const int* __restrict__ rowidx)
{
    __shared__ unsigned As[128][20];   // m-major, k padded 20: frag loads conflict-free
    __shared__ unsigned Bs[16][72];    // k-major, n padded 72: frag loads conflict-free
    int tid = threadIdx.x;
    int wid = tid >> 5, lane = tid & 31;
    int warpM = wid >> 1, warpN = wid & 1;
    int row0 = blockIdx.y * 128, col0 = blockIdx.x * 64;
    int lr = lane >> 2, lc = lane & 3;

    int am = tid >> 2, akv = (tid & 3) * 4;     // A staging: rows am, am+64; k akv..akv+3
    int bk = tid >> 4, bn4 = (tid & 15) * 4;    // B staging

    float a_st[2][4], b_st[4];
    float acc[2][4][4];
#pragma unroll
    for (int mt = 0; mt < 2; mt++)
#pragma unroll
        for (int nt = 0; nt < 4; nt++)
#pragma unroll
            for (int i = 0; i < 4; i++) acc[mt][nt][i] = 0.f;

    int KT = K / 16;

    // ---- load tile 0 into regs ----
    auto loadA = [&](int k0) {
        if (CONV) {
#pragma unroll
            for (int h = 0; h < 2; h++) {
                int r = row0 + am + h * 64;
                int b = r >> 9, t = r & 511;
#pragma unroll
                for (int j = 0; j < 4; j++) {
                    int kg = k0 + akv + j;
                    int ch = kg / 15, d = kg - ch * 15;
                    int tt = t + d - 7;
                    a_st[h][j] = (tt >= 0 && tt < PADT)
                        ? A[((size_t)(b << 9) + tt) * 128 + ch] : 0.f;
                }
            }
        } else {
            int r0 = row0 + am, r1 = row0 + am + 64;
            if (rowidx) { r0 = rowidx[r0]; r1 = rowidx[r1]; }
            float4 v0 = *(const float4*)&A[(size_t)r0 * K + k0 + akv];
            float4 v1 = *(const float4*)&A[(size_t)r1 * K + k0 + akv];
            a_st[0][0] = v0.x; a_st[0][1] = v0.y; a_st[0][2] = v0.z; a_st[0][3] = v0.w;
            a_st[1][0] = v1.x; a_st[1][1] = v1.y; a_st[1][2] = v1.z; a_st[1][3] = v1.w;
        }
    };
    auto loadB = [&](int k0) {
        float4 v = *(const float4*)&Bm[(size_t)(k0 + bk) * Nc + col0 + bn4];
        b_st[0] = v.x; b_st[1] = v.y; b_st[2] = v.z; b_st[3] = v.w;
    };

    loadA(0); loadB(0);

    for (int kt = 0; kt < KT; kt++) {
        // stage regs -> smem (tf32-converted)
        uint4 ua0 = make_uint4(f2tf(a_st[0][0]), f2tf(a_st[0][1]), f2tf(a_st[0][2]), f2tf(a_st[0][3]));
        uint4 ua1 = make_uint4(f2tf(a_st[1][0]), f2tf(a_st[1][1]), f2tf(a_st[1][2]), f2tf(a_st[1][3]));
        uint4 ub  = make_uint4(f2tf(b_st[0]), f2tf(b_st[1]), f2tf(b_st[2]), f2tf(b_st[3]));
        *(uint4*)&As[am][akv]      = ua0;
        *(uint4*)&As[am + 64][akv] = ua1;
        *(uint4*)&Bs[bk][bn4]      = ub;
        __syncthreads();

        if (kt + 1 < KT) { loadA((kt + 1) * 16); loadB((kt + 1) * 16); }

#pragma unroll
        for (int kk = 0; kk < 2; kk++) {
            int kb = kk * 8;
            unsigned af[2][4];
#pragma unroll
            for (int mt = 0; mt < 2; mt++) {
                int m = warpM * 32 + mt * 16 + lr;
                af[mt][0] = As[m][kb + lc];
                af[mt][1] = As[m + 8][kb + lc];
                af[mt][2] = As[m][kb + 4 + lc];
                af[mt][3] = As[m + 8][kb + 4 + lc];
            }
            unsigned bf[4][2];
#pragma unroll
            for (int nt = 0; nt < 4; nt++) {
                int n = warpN * 32 + nt * 8 + lr;
                bf[nt][0] = Bs[kb + lc][n];
                bf[nt][1] = Bs[kb + 4 + lc][n];
            }
#pragma unroll
            for (int mt = 0; mt < 2; mt++)
#pragma unroll
                for (int nt = 0; nt < 4; nt++)
                    mma_tf32(acc[mt][nt], af[mt], bf[nt]);
        }
        __syncthreads();
    }

    // ---- epilogue ----
#pragma unroll
    for (int mt = 0; mt < 2; mt++) {
#pragma unroll
        for (int nt = 0; nt < 4; nt++) {
            int r = row0 + warpM * 32 + mt * 16 + lr;
            int c = col0 + warpN * 32 + nt * 8 + lc * 2;
            float b0v = bias ? bias[c] : 0.f;
            float b1v = bias ? bias[c + 1] : 0.f;
            float v0 = acc[mt][nt][0] + b0v, v1 = acc[mt][nt][1] + b1v;
            float v2 = acc[mt][nt][2] + b0v, v3 = acc[mt][nt][3] + b1v;
            if (doRelu) {
                v0 = fmaxf(v0, 0.f); v1 = fmaxf(v1, 0.f);
                v2 = fmaxf(v2, 0.f); v3 = fmaxf(v3, 0.f);
            }
            *(float2*)&C[(size_t)r * Nc + c]       = make_float2(v0, v1);
            *(float2*)&C[(size_t)(r + 8) * Nc + c] = make_float2(v2, v3);
        }
    }
}

// ---------------- attention logits: a_s/a_d per (node, head) ----------------
__global__ void k_attn(const float* __restrict__ Hm, const float* __restrict__ aw,
                       const float* __restrict__ dw, int heads, int C)
{
    int n = blockIdx.x;
    int h = threadIdx.x >> 5, lane = threadIdx.x & 31;
    const float* hp = Hm + ((size_t)n * heads + h) * C;
    const float* ap = aw + h * C;
    const float* dp = dw + h * C;
    float s = 0.f, d = 0.f;
    for (int c = lane; c < C; c += 32) {
        float v = hp[c];
        s += v * ap[c];
        d += v * dp[c];
    }
    for (int o = 16; o; o >>= 1) {
        s += __shfl_xor_sync(0xFFFFFFFFu, s, o);
        d += __shfl_xor_sync(0xFFFFFFFFu, d, o);
    }
    if (!lane) { g_as[n * heads + h] = s; g_ad[n * heads + h] = d; }
}

__device__ __forceinline__ float lrelu(float z) { return z >= 0.f ? z : 0.2f * z; }

// ---------------- GAT aggregation, heads=4, C=256 ----------------
__global__ void __launch_bounds__(256) k_agg4(const float* __restrict__ Hm,
                                              const float* __restrict__ bias,
                                              float* __restrict__ out)
{
    int n = blockIdx.x, tid = threadIdx.x;
    int e0 = g_indptr[n], deg = g_indptr[n + 1] - e0;
    __shared__ float sm[4], sden[4];
    __shared__ float salpha[64 * 4];
    __shared__ int   ssrc[64];
    __shared__ float sacc[4][256];
    if (tid < 4) {
        int h = tid;
        float ad = g_ad[n * 4 + h];
        float m = -INFINITY, s = 0.f;
        for (int j = 0; j < deg; j++) {
            int src = g_col[e0 + j];
            float e = lrelu(g_as[src * 4 + h] + ad);
            if (e > m) { s = s * expf(m - e) + 1.0f; m = e; }
            else       { s += expf(e - m); }
        }
        sm[h] = m; sden[h] = fmaxf(s, 1e-16f);
    }
    __syncthreads();
    int h = tid >> 6;
    int cb = (tid & 63) * 4;
    float4 acc = make_float4(0.f, 0.f, 0.f, 0.f);
    for (int base = 0; base < deg; base += 64) {
        int cn = min(64, deg - base);
        if (tid < cn) ssrc[tid] = g_col[e0 + base + tid];
        __syncthreads();
        if (tid < cn * 4) {
            int j = tid >> 2, hh = tid & 3;
            float e = lrelu(g_as[ssrc[j] * 4 + hh] + g_ad[n * 4 + hh]);
            salpha[j * 4 + hh] = expf(e - sm[hh]) / sden[hh];
        }
        __syncthreads();
        for (int j = 0; j < cn; j++) {
            float a = salpha[j * 4 + h];
            float4 hv = *(const float4*)&Hm[((size_t)ssrc[j] * 4 + h) * 256 + cb];
            acc.x += a * hv.x; acc.y += a * hv.y;
            acc.z += a * hv.z; acc.w += a * hv.w;
        }
        __syncthreads();
    }
    *(float4*)&sacc[h][cb] = acc;
    __syncthreads();
    int c = tid;
    float v = (sacc[0][c] + sacc[1][c] + sacc[2][c] + sacc[3][c]) * 0.25f + bias[c];
    out[(size_t)n * 256 + c] = fmaxf(v, 0.f);
}

// ---------------- GAT aggregation, heads=1, C=128 ----------------
__global__ void __launch_bounds__(128) k_agg1(const float* __restrict__ Hm,
                                              const float* __restrict__ bias,
                                              float* __restrict__ out)
{
    int n = blockIdx.x, tid = threadIdx.x;
    int e0 = g_indptr[n], deg = g_indptr[n + 1] - e0;
    __shared__ float sm1, sden1;
    __shared__ float salpha[128];
    __shared__ int   ssrc[128];
    if (tid == 0) {
        float ad = g_ad[n];
        float m = -INFINITY, s = 0.f;
        for (int j = 0; j < deg; j++) {
            int src = g_col[e0 + j];
            float e = lrelu(g_as[src] + ad);
            if (e > m) { s = s * expf(m - e) + 1.0f; m = e; }
            else       { s += expf(e - m); }
        }
        sm1 = m; sden1 = fmaxf(s, 1e-16f);
    }
    __syncthreads();
    float acc = 0.f;
    for (int base = 0; base < deg; base += 128) {
        int cn = min(128, deg - base);
        if (tid < cn) {
            int src = g_col[e0 + base + tid];
            ssrc[tid] = src;
            float e = lrelu(g_as[src] + g_ad[n]);
            salpha[tid] = expf(e - sm1) / sden1;
        }
        __syncthreads();
        for (int j = 0; j < cn; j++)
            acc += salpha[j] * Hm[(size_t)ssrc[j] * 128 + tid];
        __syncthreads();
    }
    out[(size_t)n * 128 + tid] = fmaxf(acc + bias[tid], 0.f);
}

// ---------------- out_graph + masks ----------------
__global__ void k_outgraph(const int* __restrict__ node_len, float* __restrict__ out)
{
    int t = blockIdx.x, b = blockIdx.y, c = threadIdx.x;
    int len = node_len[b];
    float v = 0.f;
    if (t < len) v = g_hf[(size_t)(g_off[b] + t) * 128 + c];
    out[OFF_OG + ((size_t)b * PADT + t) * 128 + c] = v;
    if (c == 0) {
        float mk = (t < len) ? 1.f : 0.f;
        out[OFF_M1 + (size_t)b * PADT + t] = mk;
        out[OFF_M2 + (size_t)b * PADT + t] = mk;
    }
}
__global__ void k_embgraph(const int* __restrict__ node_len, float* __restrict__ out)
{
    int b = blockIdx.x, c = threadIdx.x;
    int len = node_len[b], off = g_off[b];
    float s = 0.f;
    for (int t = 0; t < len; t++) s += g_hf[(size_t)(off + t) * 128 + c];
    out[OFF_EG + (size_t)b * 128 + c] = s / g_cnt[b];
}

// ---------------- conv input: out_r = (x_r + emb2)/2, padded ----------------
__global__ void k_outr(const int* __restrict__ x, const float* __restrict__ tabr,
                       const int* __restrict__ node_len)
{
    int t = blockIdx.x, b = blockIdx.y, c = threadIdx.x;
    int len = node_len[b];
    float v = 0.f;
    if (t < len) {
        int nd = g_off[b] + t;
        v = 0.5f * (tabr[(size_t)x[nd] * 128 + c] + g_e2[(size_t)nd * 128 + c]);
    }
    g_cin[((size_t)b * PADT + t) * 128 + c] = v;
}

// ---------------- fold the three convs into one 15-tap filter, layout [ch][tap][out] ----
__global__ void k_wcomb(const float* __restrict__ cw1, const float* __restrict__ cb1,
                        const float* __restrict__ cw2, const float* __restrict__ cb2,
                        const float* __restrict__ cw3, const float* __restrict__ cb3)
{
    int i = blockIdx.x * 256 + threadIdx.x;
    if (i >= 128 * 15 * 64) return;
    int o = i & 63;
    int r = i >> 6;
    int d = r % 15;
    int ch = r / 15;
    int dd = d - 7;
    float w = cw3[((size_t)o * 128 + ch) * 15 + d];
    if (dd >= -5 && dd <= 5) w += cw2[((size_t)o * 128 + ch) * 11 + (dd + 5)];
    if (dd >= -3 && dd <= 3) w += cw1[((size_t)o * 128 + ch) * 7 + (dd + 3)];
    g_wt[(ch * 15 + d) * 64 + o] = w * (1.f / 3.f);
    if (i < 64) g_bt[i] = (cb1[i] + cb2[i] + cb3[i]) * (1.f / 3.f);
}

// ---------------- emb_seq: masked mean over PAD of out_seq_cnn ----------------
__global__ void k_embseq(const int* __restrict__ node_len, float* __restrict__ out)
{
    int b = blockIdx.x, c = threadIdx.x;
    int len = node_len[b];
    const float* p = out + OFF_CNN + (size_t)b * PADT * 128 + c;
    float s = 0.f;
    for (int t = 0; t < len; t++) s += p[(size_t)t * 128];
    out[OFF_ES + (size_t)b * 128 + c] = s * (1.0f / PADT);
}

// ======================== host ========================
extern "C" void kernel_launch(void* const* d_in, const int* in_sizes, int n_in,
                              void* d_out, int out_size)
{
    const int*   x        = (const int*)d_in[0];
    const int*   ei       = (const int*)d_in[1];
    const float* emb      = (const float*)d_in[2];
    const int*   node_len = (const int*)d_in[3];
    const int*   batch    = (const int*)d_in[4];
    const float* tab_r    = (const float*)d_in[5];
    const float* tab_g    = (const float*)d_in[6];
    const float* W1  = (const float*)d_in[7];
    const float* a1s = (const float*)d_in[8];
    const float* a1d = (const float*)d_in[9];
    const float* b1  = (const float*)d_in[10];
    const float* W2  = (const float*)d_in[11];
    const float* a2s = (const float*)d_in[12];
    const float* a2d = (const float*)d_in[13];
    const float* b2  = (const float*)d_in[14];
    const float* W3  = (const float*)d_in[15];
    const float* a3s = (const float*)d_in[16];
    const float* a3d = (const float*)d_in[17];
    const float* b3  = (const float*)d_in[18];
    const float* leW = (const float*)d_in[19];
    const float* leb = (const float*)d_in[20];
    const float* cw1 = (const float*)d_in[21];
    const float* cb1 = (const float*)d_in[22];
    const float* cw2 = (const float*)d_in[23];
    const float* cb2 = (const float*)d_in[24];
    const float* cw3 = (const float*)d_in[25];
    const float* cb3 = (const float*)d_in[26];
    const float* l1W = (const float*)d_in[27];
    const float* l1b = (const float*)d_in[28];
    const float* l2W = (const float*)d_in[29];
    const float* l2b = (const float*)d_in[30];
    float* out = (float*)d_out;

    float *ph, *px1, *px2, *pe2, *py, *phid, *phf, *pcin, *pwt, *pbt;
    int *pdeg, *pind, *pbs, *poff;
    cudaGetSymbolAddress((void**)&ph,   g_h);
    cudaGetSymbolAddress((void**)&px1,  g_x1);
    cudaGetSymbolAddress((void**)&px2,  g_x2);
    cudaGetSymbolAddress((void**)&pe2,  g_e2);
    cudaGetSymbolAddress((void**)&py,   g_y);
    cudaGetSymbolAddress((void**)&phid, g_hid);
    cudaGetSymbolAddress((void**)&phf,  g_hf);
    cudaGetSymbolAddress((void**)&pcin, g_cin);
    cudaGetSymbolAddress((void**)&pwt,  g_wt);
    cudaGetSymbolAddress((void**)&pbt,  g_bt);
    cudaGetSymbolAddress((void**)&pdeg, g_deg);
    cudaGetSymbolAddress((void**)&pind, g_indptr);
    cudaGetSymbolAddress((void**)&pbs,  g_bsum);
    cudaGetSymbolAddress((void**)&poff, g_off);

    // ---- CSR build (by dst, self-loop in slot 0) ----
    k_deg_init<<<NN / 256, 256>>>();
    k_deg_count<<<EE / 256, 256>>>(ei);
    k_scan_block<<<100, 1024>>>(pdeg, pind, pbs, NN);
    k_scan_bsums<<<1, 1024>>>(pbs, 100);
    k_scan_add<<<100, 1024>>>(pind, pbs, NN);
    k_settot<<<1, 1>>>();
    k_fill_self<<<NN / 256, 256>>>();
    k_fill_edges<<<EE / 256, 256>>>(ei);

    // ---- offsets / counts ----
    k_scan_block<<<1, 1024>>>(node_len, poff, nullptr, NB);
    k_zero_cnt<<<1, NB>>>();
    k_cnt<<<NN / 256, 256>>>(batch);

    // ---- GAT layer 1 (A-gather fused via rowidx) ----
    k_gemm_tc<0><<<dim3(16, NN / 128), 256>>>(tab_g, W1, ph, NN, 1024, 128, nullptr, 0, x);
    k_attn<<<NN, 128>>>(ph, a1s, a1d, 4, 256);
    k_agg4<<<NN, 256>>>(ph, b1, px2);

    // ---- GAT layer 2 ----
    k_gemm_tc<0><<<dim3(16, NN / 128), 256>>>(px2, W2, ph, NN, 1024, 256, nullptr, 0, nullptr);
    k_attn<<<NN, 128>>>(ph, a2s, a2d, 4, 256);
    k_agg4<<<NN, 256>>>(ph, b2, px1);

    // ---- GAT layer 3 ----
    k_gemm_tc<0><<<dim3(2, NN / 128), 256>>>(px1, W3, ph, NN, 128, 256, nullptr, 0, nullptr);
    k_attn<<<NN, 32>>>(ph, a3s, a3d, 1, 128);
    k_agg1<<<NN, 128>>>(ph, b3, phf);

    // ---- graph outputs ----
    k_outgraph<<<dim3(PADT, NB), 128>>>(node_len, out);
    k_embgraph<<<NB, 128>>>(node_len, out);

    // ---- sequence branch ----
    k_gemm_tc<0><<<dim3(2, NN / 128), 256>>>(emb, leW, pe2, NN, 128, 640, leb, 1, nullptr);
    k_outr<<<dim3(PADT, NB), 128>>>(x, tab_r, node_len);
    k_wcomb<<<480, 256>>>(cw1, cb1, cw2, cb2, cw3, cb3);
    // conv as implicit-im2col tensor GEMM: K = 128ch * 15taps = 1920
    k_gemm_tc<1><<<dim3(1, (NB * PADT) / 128), 256>>>(pcin, pwt, py, NB * PADT, 64, 1920, pbt, 0, nullptr);
    k_gemm_tc<0><<<dim3(8, (NB * PADT) / 128), 256>>>(py, l1W, phid, NB * PADT, 512, 64, l1b, 1, nullptr);
    k_gemm_tc<0><<<dim3(2, (NB * PADT) / 128), 256>>>(phid, l2W, out, NB * PADT, 128, 512, l2b, 0, nullptr);
    k_embseq<<<NB, 128>>>(node_len, out);
}